// round 13
// baseline (speedup 1.0000x reference)
#include <cuda_runtime.h>
#include <cuda_bf16.h>
#include <cstdint>

#define VOCAB 2048
#define HID   1024
#define TT    256
#define BB    128

// ---- persistent scratch (static device allocations are allowed) ----
__device__ __align__(128) __nv_bfloat16 g_Yhi[(size_t)TT * BB * HID];  // [t][m][k] hi plane, 64 MB
__device__ __align__(128) __nv_bfloat16 g_Ylo[(size_t)TT * BB * HID];  // lo plane, 64 MB
__device__ __align__(128) __nv_bfloat16 g_H0hi[BB * HID];              // h0 planes [m][k]
__device__ __align__(128) __nv_bfloat16 g_H0lo[BB * HID];
__device__ __align__(128) __nv_bfloat16 g_Whhi[(size_t)HID * HID];     // WhT hi [n][k], 2 MB
__device__ __align__(128) __nv_bfloat16 g_Whlo[(size_t)HID * HID];     // WhT lo [n][k], 2 MB
__device__ __align__(128) __nv_bfloat16 g_Bhi[(size_t)VOCAB * HID];    // WdT hi [n][k], 4 MB
__device__ __align__(128) __nv_bfloat16 g_Blo[(size_t)VOCAB * HID];    // WdT lo [n][k], 4 MB
__device__ __align__(128) float         g_ACC[BB * HID];               // step GEMM out (+bias), 512 KB

// ---------------- smem/async helpers ----------------
__device__ __forceinline__ uint32_t smem_u32(const void* p) {
    uint32_t a;
    asm("{ .reg .u64 t; cvta.to.shared.u64 t, %1; cvt.u32.u64 %0, t; }" : "=r"(a) : "l"(p));
    return a;
}
__device__ __forceinline__ void cp_async16(uint32_t sdst, const void* gsrc) {
    asm volatile("cp.async.cg.shared.global [%0], [%1], 16;" :: "r"(sdst), "l"(gsrc));
}
#define CP_COMMIT()  asm volatile("cp.async.commit_group;" ::: "memory")
#define CP_WAIT1()   asm volatile("cp.async.wait_group 1;" ::: "memory")

__device__ __forceinline__ void ldsm_x4(uint32_t r[4], uint32_t addr) {
    asm volatile("ldmatrix.sync.aligned.m8n8.x4.shared.b16 {%0,%1,%2,%3}, [%4];"
                 : "=r"(r[0]), "=r"(r[1]), "=r"(r[2]), "=r"(r[3]) : "r"(addr));
}
__device__ __forceinline__ void mma16816(float d[4], const uint32_t a[4], const uint32_t b0,
                                         const uint32_t b1) {
    asm volatile(
        "mma.sync.aligned.m16n8k16.row.col.f32.bf16.bf16.f32 "
        "{%0,%1,%2,%3}, {%4,%5,%6,%7}, {%8,%9}, {%0,%1,%2,%3};"
        : "+f"(d[0]), "+f"(d[1]), "+f"(d[2]), "+f"(d[3])
        : "r"(a[0]), "r"(a[1]), "r"(a[2]), "r"(a[3]), "r"(b0), "r"(b1));
}

// ---------------- init: split h0 (state, [m][k] row-major) into planes ----------------
__global__ void init_kernel(const float* __restrict__ state) {
    int idx = blockIdx.x * 256 + threadIdx.x;       // 131072 total
    float v = state[idx];
    __nv_bfloat16 h = __float2bfloat16_rn(v);
    __nv_bfloat16 l = __float2bfloat16_rn(v - __bfloat162float(h));
    g_H0hi[idx] = h;
    g_H0lo[idx] = l;
}

// ---------------- Wd prep (verified R4): transpose + bf16 hi/lo split ----------------
__global__ void __launch_bounds__(256)
wd_prep(const float* __restrict__ Wd) {
    __shared__ float ts[32][33];
    const int n0 = blockIdx.x * 32, k0 = blockIdx.y * 32;
    const int tx = threadIdx.x & 31, ty = threadIdx.x >> 5;
#pragma unroll
    for (int j = 0; j < 4; j++)
        ts[ty + 8 * j][tx] = Wd[(size_t)(k0 + ty + 8 * j) * VOCAB + n0 + tx];
    __syncthreads();
#pragma unroll
    for (int j = 0; j < 4; j++) {
        float v = ts[tx][ty + 8 * j];
        __nv_bfloat16 h = __float2bfloat16_rn(v);
        __nv_bfloat16 l = __float2bfloat16_rn(v - __bfloat162float(h));
        size_t o = (size_t)(n0 + ty + 8 * j) * HID + k0 + tx;
        g_Bhi[o] = h;
        g_Blo[o] = l;
    }
}

// ---------------- Wh prep: same pattern, square HID x HID ----------------
__global__ void __launch_bounds__(256)
wh_prep(const float* __restrict__ Wh) {
    __shared__ float ts[32][33];
    const int n0 = blockIdx.x * 32, k0 = blockIdx.y * 32;
    const int tx = threadIdx.x & 31, ty = threadIdx.x >> 5;
#pragma unroll
    for (int j = 0; j < 4; j++)
        ts[ty + 8 * j][tx] = Wh[(size_t)(k0 + ty + 8 * j) * HID + n0 + tx];
    __syncthreads();
#pragma unroll
    for (int j = 0; j < 4; j++) {
        float v = ts[tx][ty + 8 * j];
        __nv_bfloat16 h = __float2bfloat16_rn(v);
        __nv_bfloat16 l = __float2bfloat16_rn(v - __bfloat162float(h));
        size_t o = (size_t)(n0 + ty + 8 * j) * HID + k0 + tx;
        g_Whhi[o] = h;
        g_Whlo[o] = l;
    }
}

// =====================================================================
// Shared GEMM geometry (decoder-verified): BM=128, BN=128, BK=64,
// 256 thr (8 warps, 2m x 4n grid of 64x32 warp tiles), cp.async
// double-buffered stages: Ah 16K | Al 16K | Bh 16K | Bl 16K = 64KB.
// =====================================================================
#define DEC_STAGE 65536
#define DEC_SMEM  (2 * DEC_STAGE)

// =====================================================================
// gemm_step: decoder_mma clone. grid=(8,1).
//   g_ACC[128m, n-block] = hplanes[t-1] @ WhT-planes + bias
// Epilogue is the decoder's epilogue verbatim (acc + bv, float2 stores),
// only the output stride (HID) and destination (g_ACC) differ.
// =====================================================================
__global__ void __launch_bounds__(256, 1)
gemm_step(const float* __restrict__ bias, int t)
{
    extern __shared__ __align__(128) char dsm[];
    const uint32_t sbase = smem_u32(dsm);

    const int tid  = threadIdx.x;
    const int lane = tid & 31;
    const int wid  = tid >> 5;
    const int wm   = wid >> 2;          // 0..1
    const int wn   = wid & 3;           // 0..3
    const int n0g  = blockIdx.x * 128;  // hidden-col block

    const __nv_bfloat16* __restrict__ gAh =
        (t == 0) ? g_H0hi : (g_Yhi + (size_t)(t - 1) * BB * HID);
    const __nv_bfloat16* __restrict__ gAl =
        (t == 0) ? g_H0lo : (g_Ylo + (size_t)(t - 1) * BB * HID);
    const __nv_bfloat16* __restrict__ gBh = g_Whhi + (size_t)n0g * HID;
    const __nv_bfloat16* __restrict__ gBl = g_Whlo + (size_t)n0g * HID;

    auto issue_stage = [&](int stage, int k0) {
        const uint32_t sb = sbase + stage * DEC_STAGE;
#pragma unroll
        for (int j = 0; j < 4; j++) {
            int c   = tid + 256 * j;
            int row = c >> 3, cx = c & 7;
            uint32_t soff = (uint32_t)(row * 128 + ((cx * 16) ^ ((row & 7) << 4)));
            size_t goff = (size_t)row * HID + k0 + cx * 8;
            cp_async16(sb + soff,         gAh + goff);
            cp_async16(sb + 16384 + soff, gAl + goff);
            cp_async16(sb + 32768 + soff, gBh + goff);
            cp_async16(sb + 49152 + soff, gBl + goff);
        }
    };

    const int roffA = (lane & 7) + ((lane >> 3) & 1) * 8;
    const int kaddA = (lane >> 4) & 1;
    const int roffB = (lane & 7) + ((lane >> 4) & 1) * 8;
    const int kaddB = (lane >> 3) & 1;
    const int swx   = (lane & 7) << 4;
    const uint32_t rowA = (uint32_t)((wm * 64 + roffA) * 128);
    const uint32_t rowB = (uint32_t)((wn * 32 + roffB) * 128);

    float acc[4][4][4];
#pragma unroll
    for (int i = 0; i < 4; i++)
#pragma unroll
        for (int j = 0; j < 4; j++)
#pragma unroll
            for (int q = 0; q < 4; q++) acc[i][j][q] = 0.f;

    issue_stage(0, 0);
    CP_COMMIT();

    for (int it = 0; it < 16; it++) {
        if (it + 1 < 16) issue_stage((it + 1) & 1, (it + 1) * 64);
        CP_COMMIT();
        CP_WAIT1();
        __syncthreads();

        const uint32_t sb = sbase + (it & 1) * DEC_STAGE;
        const uint32_t pAh = sb,          pAl = sb + 16384;
        const uint32_t pBh = sb + 32768,  pBl = sb + 49152;

#pragma unroll
        for (int kk = 0; kk < 4; kk++) {
            const uint32_t kA = (uint32_t)((kk * 32 + kaddA * 16) ^ swx);
            const uint32_t kB = (uint32_t)((kk * 32 + kaddB * 16) ^ swx);

            uint32_t ah[4][4], al[4][4];
#pragma unroll
            for (int mt = 0; mt < 4; mt++) {
                ldsm_x4(ah[mt], pAh + rowA + mt * 2048 + kA);
                ldsm_x4(al[mt], pAl + rowA + mt * 2048 + kA);
            }
            uint32_t bh[2][4], bl[2][4];
#pragma unroll
            for (int np = 0; np < 2; np++) {
                ldsm_x4(bh[np], pBh + rowB + np * 2048 + kB);
                ldsm_x4(bl[np], pBl + rowB + np * 2048 + kB);
            }
#pragma unroll
            for (int mt = 0; mt < 4; mt++) {
#pragma unroll
                for (int nt = 0; nt < 4; nt++) {
                    const int np = nt >> 1, ni = (nt & 1) * 2;
                    mma16816(acc[mt][nt], ah[mt], bh[np][ni], bh[np][ni + 1]);
                    mma16816(acc[mt][nt], ah[mt], bl[np][ni], bl[np][ni + 1]);
                    mma16816(acc[mt][nt], al[mt], bh[np][ni], bh[np][ni + 1]);
                }
            }
        }
        __syncthreads();
    }

    // ---- decoder epilogue verbatim: out -> g_ACC, stride HID, bd -> bias ----
    const int rbase = wm * 64 + (lane >> 2);
    const int cbase = n0g + wn * 32 + (lane & 3) * 2;
#pragma unroll
    for (int mt = 0; mt < 4; mt++) {
#pragma unroll
        for (int nt = 0; nt < 4; nt++) {
            const int col = cbase + nt * 8;
            const float2 bv = *(const float2*)&bias[col];
            const int r0 = rbase + mt * 16;
            float2 v0 = make_float2(acc[mt][nt][0] + bv.x, acc[mt][nt][1] + bv.y);
            float2 v1 = make_float2(acc[mt][nt][2] + bv.x, acc[mt][nt][3] + bv.y);
            *(float2*)&g_ACC[(size_t)r0 * HID + col]       = v0;
            *(float2*)&g_ACC[(size_t)(r0 + 8) * HID + col] = v1;
        }
    }
}

// =====================================================================
// act_step: h = tanh(g_ACC + Wx[tok]) -> bf16 hi/lo planes[t]
// (g_ACC already includes bias). grid = 512 x 256 thr; 1 elem/thread.
// =====================================================================
__global__ void __launch_bounds__(256)
act_step(const int* __restrict__ inputs, const float* __restrict__ Wx,
         float* __restrict__ hfin, int t)
{
    int idx = blockIdx.x * 256 + threadIdx.x;   // 0..131071
    int m = idx >> 10;
    int n = idx & 1023;
    int tok = inputs[m * TT + t];
    float s = g_ACC[idx] + Wx[(size_t)tok * HID + n];
    float h = tanhf(s);
    __nv_bfloat16 hh = __float2bfloat16_rn(h);
    __nv_bfloat16 hl = __float2bfloat16_rn(h - __bfloat162float(hh));
    size_t o = (size_t)t * BB * HID + idx;
    g_Yhi[o] = hh;
    g_Ylo[o] = hl;
    if (t == TT - 1) hfin[idx] = h;
}

// =====================================================================
// Decoder on mma.sync bf16 (2-term split) — unchanged (verified R4).
// =====================================================================
__global__ void __launch_bounds__(256, 1)
decoder_mma(const float* __restrict__ bd, float* __restrict__ out)
{
    extern __shared__ __align__(128) char dsm[];
    const uint32_t sbase = smem_u32(dsm);

    const int tid  = threadIdx.x;
    const int lane = tid & 31;
    const int wid  = tid >> 5;
    const int wm   = wid >> 2;          // 0..1
    const int wn   = wid & 3;           // 0..3
    const int mblk = blockIdx.y;        // 0..255 (= timestep)
    const int n0g  = blockIdx.x * 128;  // global n offset

    const __nv_bfloat16* __restrict__ gAh = g_Yhi + (size_t)mblk * 128 * HID;
    const __nv_bfloat16* __restrict__ gAl = g_Ylo + (size_t)mblk * 128 * HID;
    const __nv_bfloat16* __restrict__ gBh = g_Bhi + (size_t)n0g * HID;
    const __nv_bfloat16* __restrict__ gBl = g_Blo + (size_t)n0g * HID;

    auto issue_stage = [&](int stage, int k0) {
        const uint32_t sb = sbase + stage * DEC_STAGE;
#pragma unroll
        for (int j = 0; j < 4; j++) {
            int c   = tid + 256 * j;
            int row = c >> 3, cx = c & 7;
            uint32_t soff = (uint32_t)(row * 128 + ((cx * 16) ^ ((row & 7) << 4)));
            size_t goff = (size_t)row * HID + k0 + cx * 8;
            cp_async16(sb + soff,         gAh + goff);
            cp_async16(sb + 16384 + soff, gAl + goff);
            cp_async16(sb + 32768 + soff, gBh + goff);
            cp_async16(sb + 49152 + soff, gBl + goff);
        }
    };

    const int roffA = (lane & 7) + ((lane >> 3) & 1) * 8;
    const int kaddA = (lane >> 4) & 1;
    const int roffB = (lane & 7) + ((lane >> 4) & 1) * 8;
    const int kaddB = (lane >> 3) & 1;
    const int swx   = (lane & 7) << 4;
    const uint32_t rowA = (uint32_t)((wm * 64 + roffA) * 128);
    const uint32_t rowB = (uint32_t)((wn * 32 + roffB) * 128);

    float acc[4][4][4];
#pragma unroll
    for (int i = 0; i < 4; i++)
#pragma unroll
        for (int j = 0; j < 4; j++)
#pragma unroll
            for (int q = 0; q < 4; q++) acc[i][j][q] = 0.f;

    issue_stage(0, 0);
    CP_COMMIT();

    for (int it = 0; it < 16; it++) {
        if (it + 1 < 16) issue_stage((it + 1) & 1, (it + 1) * 64);
        CP_COMMIT();
        CP_WAIT1();
        __syncthreads();

        const uint32_t sb = sbase + (it & 1) * DEC_STAGE;
        const uint32_t pAh = sb,          pAl = sb + 16384;
        const uint32_t pBh = sb + 32768,  pBl = sb + 49152;

#pragma unroll
        for (int kk = 0; kk < 4; kk++) {
            const uint32_t kA = (uint32_t)((kk * 32 + kaddA * 16) ^ swx);
            const uint32_t kB = (uint32_t)((kk * 32 + kaddB * 16) ^ swx);

            uint32_t ah[4][4], al[4][4];
#pragma unroll
            for (int mt = 0; mt < 4; mt++) {
                ldsm_x4(ah[mt], pAh + rowA + mt * 2048 + kA);
                ldsm_x4(al[mt], pAl + rowA + mt * 2048 + kA);
            }
            uint32_t bh[2][4], bl[2][4];
#pragma unroll
            for (int np = 0; np < 2; np++) {
                ldsm_x4(bh[np], pBh + rowB + np * 2048 + kB);
                ldsm_x4(bl[np], pBl + rowB + np * 2048 + kB);
            }
#pragma unroll
            for (int mt = 0; mt < 4; mt++) {
#pragma unroll
                for (int nt = 0; nt < 4; nt++) {
                    const int np = nt >> 1, ni = (nt & 1) * 2;
                    mma16816(acc[mt][nt], ah[mt], bh[np][ni], bh[np][ni + 1]);
                    mma16816(acc[mt][nt], ah[mt], bl[np][ni], bl[np][ni + 1]);
                    mma16816(acc[mt][nt], al[mt], bh[np][ni], bh[np][ni + 1]);
                }
            }
        }
        __syncthreads();
    }

    const int rbase = mblk * 128 + wm * 64 + (lane >> 2);
    const int cbase = n0g + wn * 32 + (lane & 3) * 2;
#pragma unroll
    for (int mt = 0; mt < 4; mt++) {
#pragma unroll
        for (int nt = 0; nt < 4; nt++) {
            const int col = cbase + nt * 8;
            const float2 bv = *(const float2*)&bd[col];
            const int r0 = rbase + mt * 16;
            float2 v0 = make_float2(acc[mt][nt][0] + bv.x, acc[mt][nt][1] + bv.y);
            float2 v1 = make_float2(acc[mt][nt][2] + bv.x, acc[mt][nt][3] + bv.y);
            *(float2*)&out[(size_t)r0 * VOCAB + col]       = v0;
            *(float2*)&out[(size_t)(r0 + 8) * VOCAB + col] = v1;
        }
    }
}

extern "C" void kernel_launch(void* const* d_in, const int* in_sizes, int n_in,
                              void* d_out, int out_size)
{
    const int*   inputs = (const int*)  d_in[0];
    const float* state  = (const float*)d_in[1];
    const float* Wx     = (const float*)d_in[2];
    const float* Wh     = (const float*)d_in[3];
    const float* bias   = (const float*)d_in[4];
    const float* Wd     = (const float*)d_in[5];
    const float* bd     = (const float*)d_in[6];
    float* out = (float*)d_out;

    cudaFuncSetAttribute(gemm_step,   cudaFuncAttributeMaxDynamicSharedMemorySize, DEC_SMEM);
    cudaFuncSetAttribute(decoder_mma, cudaFuncAttributeMaxDynamicSharedMemorySize, DEC_SMEM);

    size_t hf_off = (size_t)out_size - (size_t)BB * HID;
    float* hfin = out + hf_off;

    // launch #1: h0 planes
    init_kernel<<<(BB * HID) / 256, 256>>>(state);

    // launch #2: WdT planes (verified wd_prep)
    dim3 gridWd(VOCAB / 32, HID / 32);
    wd_prep<<<gridWd, 256>>>(Wd);

    // launch #3: WhT planes
    dim3 gridWh(HID / 32, HID / 32);
    wh_prep<<<gridWh, 256>>>(Wh);

    // launches #4..: recurrence = per-step (GEMM kernel, activation kernel)
    for (int t = 0; t < TT; t++) {
        gemm_step<<<dim3(HID / 128, 1), 256, DEC_SMEM>>>(bias, t);
        act_step<<<(BB * HID) / 256, 256>>>(inputs, Wx, hfin, t);
    }

    // decoder over all timesteps
    dim3 gridD(VOCAB / 128, TT);   // (16, 256)
    decoder_mma<<<gridD, 256, DEC_SMEM>>>(bd, out);
}

// round 14
// speedup vs baseline: 3.2318x; 3.2318x over previous
#include <cuda_runtime.h>
#include <cuda_bf16.h>
#include <cstdint>

#define VOCAB 2048
#define HID   1024
#define TT    256
#define BB    128
#define KSPLIT 8           // K-split factor for the per-step GEMM

// ---- persistent scratch (static device allocations are allowed) ----
__device__ __align__(128) __nv_bfloat16 g_Yhi[(size_t)TT * BB * HID];  // [t][m][k] hi plane, 64 MB
__device__ __align__(128) __nv_bfloat16 g_Ylo[(size_t)TT * BB * HID];  // lo plane, 64 MB
__device__ __align__(128) __nv_bfloat16 g_H0hi[BB * HID];              // h0 planes [m][k]
__device__ __align__(128) __nv_bfloat16 g_H0lo[BB * HID];
__device__ __align__(128) __nv_bfloat16 g_Whhi[(size_t)HID * HID];     // WhT hi [n][k], 2 MB
__device__ __align__(128) __nv_bfloat16 g_Whlo[(size_t)HID * HID];     // WhT lo [n][k], 2 MB
__device__ __align__(128) __nv_bfloat16 g_Bhi[(size_t)VOCAB * HID];    // WdT hi [n][k], 4 MB
__device__ __align__(128) __nv_bfloat16 g_Blo[(size_t)VOCAB * HID];    // WdT lo [n][k], 4 MB
__device__ __align__(128) float         g_PACC[KSPLIT * BB * HID];     // k-split partials, 4 MB

// ---------------- smem/async helpers ----------------
__device__ __forceinline__ uint32_t smem_u32(const void* p) {
    uint32_t a;
    asm("{ .reg .u64 t; cvta.to.shared.u64 t, %1; cvt.u32.u64 %0, t; }" : "=r"(a) : "l"(p));
    return a;
}
__device__ __forceinline__ void cp_async16(uint32_t sdst, const void* gsrc) {
    asm volatile("cp.async.cg.shared.global [%0], [%1], 16;" :: "r"(sdst), "l"(gsrc));
}
#define CP_COMMIT()  asm volatile("cp.async.commit_group;" ::: "memory")
#define CP_WAIT1()   asm volatile("cp.async.wait_group 1;" ::: "memory")

__device__ __forceinline__ void ldsm_x4(uint32_t r[4], uint32_t addr) {
    asm volatile("ldmatrix.sync.aligned.m8n8.x4.shared.b16 {%0,%1,%2,%3}, [%4];"
                 : "=r"(r[0]), "=r"(r[1]), "=r"(r[2]), "=r"(r[3]) : "r"(addr));
}
__device__ __forceinline__ void mma16816(float d[4], const uint32_t a[4], const uint32_t b0,
                                         const uint32_t b1) {
    asm volatile(
        "mma.sync.aligned.m16n8k16.row.col.f32.bf16.bf16.f32 "
        "{%0,%1,%2,%3}, {%4,%5,%6,%7}, {%8,%9}, {%0,%1,%2,%3};"
        : "+f"(d[0]), "+f"(d[1]), "+f"(d[2]), "+f"(d[3])
        : "r"(a[0]), "r"(a[1]), "r"(a[2]), "r"(a[3]), "r"(b0), "r"(b1));
}

// ---------------- init: split h0 (state, [m][k] row-major) into planes ----------------
__global__ void init_kernel(const float* __restrict__ state) {
    int idx = blockIdx.x * 256 + threadIdx.x;       // 131072 total
    float v = state[idx];
    __nv_bfloat16 h = __float2bfloat16_rn(v);
    __nv_bfloat16 l = __float2bfloat16_rn(v - __bfloat162float(h));
    g_H0hi[idx] = h;
    g_H0lo[idx] = l;
}

// ---------------- Wd prep (verified R4): transpose + bf16 hi/lo split ----------------
__global__ void __launch_bounds__(256)
wd_prep(const float* __restrict__ Wd) {
    __shared__ float ts[32][33];
    const int n0 = blockIdx.x * 32, k0 = blockIdx.y * 32;
    const int tx = threadIdx.x & 31, ty = threadIdx.x >> 5;
#pragma unroll
    for (int j = 0; j < 4; j++)
        ts[ty + 8 * j][tx] = Wd[(size_t)(k0 + ty + 8 * j) * VOCAB + n0 + tx];
    __syncthreads();
#pragma unroll
    for (int j = 0; j < 4; j++) {
        float v = ts[tx][ty + 8 * j];
        __nv_bfloat16 h = __float2bfloat16_rn(v);
        __nv_bfloat16 l = __float2bfloat16_rn(v - __bfloat162float(h));
        size_t o = (size_t)(n0 + ty + 8 * j) * HID + k0 + tx;
        g_Bhi[o] = h;
        g_Blo[o] = l;
    }
}

// ---------------- Wh prep: same pattern, square HID x HID (verified R13) ----------------
__global__ void __launch_bounds__(256)
wh_prep(const float* __restrict__ Wh) {
    __shared__ float ts[32][33];
    const int n0 = blockIdx.x * 32, k0 = blockIdx.y * 32;
    const int tx = threadIdx.x & 31, ty = threadIdx.x >> 5;
#pragma unroll
    for (int j = 0; j < 4; j++)
        ts[ty + 8 * j][tx] = Wh[(size_t)(k0 + ty + 8 * j) * HID + n0 + tx];
    __syncthreads();
#pragma unroll
    for (int j = 0; j < 4; j++) {
        float v = ts[tx][ty + 8 * j];
        __nv_bfloat16 h = __float2bfloat16_rn(v);
        __nv_bfloat16 l = __float2bfloat16_rn(v - __bfloat162float(h));
        size_t o = (size_t)(n0 + ty + 8 * j) * HID + k0 + tx;
        g_Whhi[o] = h;
        g_Whlo[o] = l;
    }
}

// =====================================================================
// Shared GEMM geometry (decoder-verified): BM=128, BN=128, BK=64,
// 256 thr (8 warps, 2m x 4n grid of 64x32 warp tiles), cp.async
// double-buffered stages: Ah 16K | Al 16K | Bh 16K | Bl 16K = 64KB.
// =====================================================================
#define DEC_STAGE 65536
#define DEC_SMEM  (2 * DEC_STAGE)

// =====================================================================
// gemm_step (R13-verified mainloop, k-split): grid=(8, KSPLIT).
//   blockIdx.x = n-block (128 cols), blockIdx.y = ky (K range ky*128,+128)
//   => 2 double-buffered stages per CTA instead of 16.
//   Partial (no bias) -> g_PACC[ky][m][n].
// =====================================================================
__global__ void __launch_bounds__(256, 1)
gemm_step(int t)
{
    extern __shared__ __align__(128) char dsm[];
    const uint32_t sbase = smem_u32(dsm);

    const int tid  = threadIdx.x;
    const int lane = tid & 31;
    const int wid  = tid >> 5;
    const int wm   = wid >> 2;          // 0..1
    const int wn   = wid & 3;           // 0..3
    const int n0g  = blockIdx.x * 128;  // hidden-col block
    const int ky   = blockIdx.y;        // k-split index
    const int kbase = ky * (HID / KSPLIT);   // 128 k per split

    const __nv_bfloat16* __restrict__ gAh =
        (t == 0) ? g_H0hi : (g_Yhi + (size_t)(t - 1) * BB * HID);
    const __nv_bfloat16* __restrict__ gAl =
        (t == 0) ? g_H0lo : (g_Ylo + (size_t)(t - 1) * BB * HID);
    const __nv_bfloat16* __restrict__ gBh = g_Whhi + (size_t)n0g * HID;
    const __nv_bfloat16* __restrict__ gBl = g_Whlo + (size_t)n0g * HID;

    auto issue_stage = [&](int stage, int k0) {
        const uint32_t sb = sbase + stage * DEC_STAGE;
#pragma unroll
        for (int j = 0; j < 4; j++) {
            int c   = tid + 256 * j;
            int row = c >> 3, cx = c & 7;
            uint32_t soff = (uint32_t)(row * 128 + ((cx * 16) ^ ((row & 7) << 4)));
            size_t goff = (size_t)row * HID + k0 + cx * 8;
            cp_async16(sb + soff,         gAh + goff);
            cp_async16(sb + 16384 + soff, gAl + goff);
            cp_async16(sb + 32768 + soff, gBh + goff);
            cp_async16(sb + 49152 + soff, gBl + goff);
        }
    };

    const int roffA = (lane & 7) + ((lane >> 3) & 1) * 8;
    const int kaddA = (lane >> 4) & 1;
    const int roffB = (lane & 7) + ((lane >> 4) & 1) * 8;
    const int kaddB = (lane >> 3) & 1;
    const int swx   = (lane & 7) << 4;
    const uint32_t rowA = (uint32_t)((wm * 64 + roffA) * 128);
    const uint32_t rowB = (uint32_t)((wn * 32 + roffB) * 128);

    float acc[4][4][4];
#pragma unroll
    for (int i = 0; i < 4; i++)
#pragma unroll
        for (int j = 0; j < 4; j++)
#pragma unroll
            for (int q = 0; q < 4; q++) acc[i][j][q] = 0.f;

    const int NIT = (HID / KSPLIT) / 64;    // 2 stages

    issue_stage(0, kbase);
    CP_COMMIT();

    for (int it = 0; it < NIT; it++) {
        if (it + 1 < NIT) issue_stage((it + 1) & 1, kbase + (it + 1) * 64);
        CP_COMMIT();
        CP_WAIT1();
        __syncthreads();

        const uint32_t sb = sbase + (it & 1) * DEC_STAGE;
        const uint32_t pAh = sb,          pAl = sb + 16384;
        const uint32_t pBh = sb + 32768,  pBl = sb + 49152;

#pragma unroll
        for (int kk = 0; kk < 4; kk++) {
            const uint32_t kA = (uint32_t)((kk * 32 + kaddA * 16) ^ swx);
            const uint32_t kB = (uint32_t)((kk * 32 + kaddB * 16) ^ swx);

            uint32_t ah[4][4], al[4][4];
#pragma unroll
            for (int mt = 0; mt < 4; mt++) {
                ldsm_x4(ah[mt], pAh + rowA + mt * 2048 + kA);
                ldsm_x4(al[mt], pAl + rowA + mt * 2048 + kA);
            }
            uint32_t bh[2][4], bl[2][4];
#pragma unroll
            for (int np = 0; np < 2; np++) {
                ldsm_x4(bh[np], pBh + rowB + np * 2048 + kB);
                ldsm_x4(bl[np], pBl + rowB + np * 2048 + kB);
            }
#pragma unroll
            for (int mt = 0; mt < 4; mt++) {
#pragma unroll
                for (int nt = 0; nt < 4; nt++) {
                    const int np = nt >> 1, ni = (nt & 1) * 2;
                    mma16816(acc[mt][nt], ah[mt], bh[np][ni], bh[np][ni + 1]);
                    mma16816(acc[mt][nt], ah[mt], bl[np][ni], bl[np][ni + 1]);
                    mma16816(acc[mt][nt], al[mt], bh[np][ni], bh[np][ni + 1]);
                }
            }
        }
        __syncthreads();
    }

    // ---- epilogue (decoder pattern): raw partials -> g_PACC[ky] ----
    float* __restrict__ pacc = g_PACC + (size_t)ky * BB * HID;
    const int rbase = wm * 64 + (lane >> 2);
    const int cbase = n0g + wn * 32 + (lane & 3) * 2;
#pragma unroll
    for (int mt = 0; mt < 4; mt++) {
#pragma unroll
        for (int nt = 0; nt < 4; nt++) {
            const int col = cbase + nt * 8;
            const int r0 = rbase + mt * 16;
            float2 v0 = make_float2(acc[mt][nt][0], acc[mt][nt][1]);
            float2 v1 = make_float2(acc[mt][nt][2], acc[mt][nt][3]);
            *(float2*)&pacc[(size_t)r0 * HID + col]       = v0;
            *(float2*)&pacc[(size_t)(r0 + 8) * HID + col] = v1;
        }
    }
}

// =====================================================================
// act_step: h = tanh(sum_ky PACC[ky] + bias + Wx[tok]) -> bf16 planes[t]
// grid = 512 x 256 thr; 1 elem/thread.
// =====================================================================
__global__ void __launch_bounds__(256)
act_step(const int* __restrict__ inputs, const float* __restrict__ Wx,
         const float* __restrict__ bias, float* __restrict__ hfin, int t)
{
    int idx = blockIdx.x * 256 + threadIdx.x;   // 0..131071
    int m = idx >> 10;
    int n = idx & 1023;
    int tok = inputs[m * TT + t];
    float s = bias[n] + Wx[(size_t)tok * HID + n];
#pragma unroll
    for (int ky = 0; ky < KSPLIT; ky++)
        s += g_PACC[(size_t)ky * BB * HID + idx];
    float h = tanhf(s);
    __nv_bfloat16 hh = __float2bfloat16_rn(h);
    __nv_bfloat16 hl = __float2bfloat16_rn(h - __bfloat162float(hh));
    size_t o = (size_t)t * BB * HID + idx;
    g_Yhi[o] = hh;
    g_Ylo[o] = hl;
    if (t == TT - 1) hfin[idx] = h;
}

// =====================================================================
// Decoder on mma.sync bf16 (2-term split) — unchanged (verified R4).
// =====================================================================
__global__ void __launch_bounds__(256, 1)
decoder_mma(const float* __restrict__ bd, float* __restrict__ out)
{
    extern __shared__ __align__(128) char dsm[];
    const uint32_t sbase = smem_u32(dsm);

    const int tid  = threadIdx.x;
    const int lane = tid & 31;
    const int wid  = tid >> 5;
    const int wm   = wid >> 2;          // 0..1
    const int wn   = wid & 3;           // 0..3
    const int mblk = blockIdx.y;        // 0..255 (= timestep)
    const int n0g  = blockIdx.x * 128;  // global n offset

    const __nv_bfloat16* __restrict__ gAh = g_Yhi + (size_t)mblk * 128 * HID;
    const __nv_bfloat16* __restrict__ gAl = g_Ylo + (size_t)mblk * 128 * HID;
    const __nv_bfloat16* __restrict__ gBh = g_Bhi + (size_t)n0g * HID;
    const __nv_bfloat16* __restrict__ gBl = g_Blo + (size_t)n0g * HID;

    auto issue_stage = [&](int stage, int k0) {
        const uint32_t sb = sbase + stage * DEC_STAGE;
#pragma unroll
        for (int j = 0; j < 4; j++) {
            int c   = tid + 256 * j;
            int row = c >> 3, cx = c & 7;
            uint32_t soff = (uint32_t)(row * 128 + ((cx * 16) ^ ((row & 7) << 4)));
            size_t goff = (size_t)row * HID + k0 + cx * 8;
            cp_async16(sb + soff,         gAh + goff);
            cp_async16(sb + 16384 + soff, gAl + goff);
            cp_async16(sb + 32768 + soff, gBh + goff);
            cp_async16(sb + 49152 + soff, gBl + goff);
        }
    };

    const int roffA = (lane & 7) + ((lane >> 3) & 1) * 8;
    const int kaddA = (lane >> 4) & 1;
    const int roffB = (lane & 7) + ((lane >> 4) & 1) * 8;
    const int kaddB = (lane >> 3) & 1;
    const int swx   = (lane & 7) << 4;
    const uint32_t rowA = (uint32_t)((wm * 64 + roffA) * 128);
    const uint32_t rowB = (uint32_t)((wn * 32 + roffB) * 128);

    float acc[4][4][4];
#pragma unroll
    for (int i = 0; i < 4; i++)
#pragma unroll
        for (int j = 0; j < 4; j++)
#pragma unroll
            for (int q = 0; q < 4; q++) acc[i][j][q] = 0.f;

    issue_stage(0, 0);
    CP_COMMIT();

    for (int it = 0; it < 16; it++) {
        if (it + 1 < 16) issue_stage((it + 1) & 1, (it + 1) * 64);
        CP_COMMIT();
        CP_WAIT1();
        __syncthreads();

        const uint32_t sb = sbase + (it & 1) * DEC_STAGE;
        const uint32_t pAh = sb,          pAl = sb + 16384;
        const uint32_t pBh = sb + 32768,  pBl = sb + 49152;

#pragma unroll
        for (int kk = 0; kk < 4; kk++) {
            const uint32_t kA = (uint32_t)((kk * 32 + kaddA * 16) ^ swx);
            const uint32_t kB = (uint32_t)((kk * 32 + kaddB * 16) ^ swx);

            uint32_t ah[4][4], al[4][4];
#pragma unroll
            for (int mt = 0; mt < 4; mt++) {
                ldsm_x4(ah[mt], pAh + rowA + mt * 2048 + kA);
                ldsm_x4(al[mt], pAl + rowA + mt * 2048 + kA);
            }
            uint32_t bh[2][4], bl[2][4];
#pragma unroll
            for (int np = 0; np < 2; np++) {
                ldsm_x4(bh[np], pBh + rowB + np * 2048 + kB);
                ldsm_x4(bl[np], pBl + rowB + np * 2048 + kB);
            }
#pragma unroll
            for (int mt = 0; mt < 4; mt++) {
#pragma unroll
                for (int nt = 0; nt < 4; nt++) {
                    const int np = nt >> 1, ni = (nt & 1) * 2;
                    mma16816(acc[mt][nt], ah[mt], bh[np][ni], bh[np][ni + 1]);
                    mma16816(acc[mt][nt], ah[mt], bl[np][ni], bl[np][ni + 1]);
                    mma16816(acc[mt][nt], al[mt], bh[np][ni], bh[np][ni + 1]);
                }
            }
        }
        __syncthreads();
    }

    const int rbase = mblk * 128 + wm * 64 + (lane >> 2);
    const int cbase = n0g + wn * 32 + (lane & 3) * 2;
#pragma unroll
    for (int mt = 0; mt < 4; mt++) {
#pragma unroll
        for (int nt = 0; nt < 4; nt++) {
            const int col = cbase + nt * 8;
            const float2 bv = *(const float2*)&bd[col];
            const int r0 = rbase + mt * 16;
            float2 v0 = make_float2(acc[mt][nt][0] + bv.x, acc[mt][nt][1] + bv.y);
            float2 v1 = make_float2(acc[mt][nt][2] + bv.x, acc[mt][nt][3] + bv.y);
            *(float2*)&out[(size_t)r0 * VOCAB + col]       = v0;
            *(float2*)&out[(size_t)(r0 + 8) * VOCAB + col] = v1;
        }
    }
}

extern "C" void kernel_launch(void* const* d_in, const int* in_sizes, int n_in,
                              void* d_out, int out_size)
{
    const int*   inputs = (const int*)  d_in[0];
    const float* state  = (const float*)d_in[1];
    const float* Wx     = (const float*)d_in[2];
    const float* Wh     = (const float*)d_in[3];
    const float* bias   = (const float*)d_in[4];
    const float* Wd     = (const float*)d_in[5];
    const float* bd     = (const float*)d_in[6];
    float* out = (float*)d_out;

    cudaFuncSetAttribute(gemm_step,   cudaFuncAttributeMaxDynamicSharedMemorySize, DEC_SMEM);
    cudaFuncSetAttribute(decoder_mma, cudaFuncAttributeMaxDynamicSharedMemorySize, DEC_SMEM);

    size_t hf_off = (size_t)out_size - (size_t)BB * HID;
    float* hfin = out + hf_off;

    // launch #1: h0 planes
    init_kernel<<<(BB * HID) / 256, 256>>>(state);

    // launch #2: WdT planes
    dim3 gridWd(VOCAB / 32, HID / 32);
    wd_prep<<<gridWd, 256>>>(Wd);

    // launch #3: WhT planes
    dim3 gridWh(HID / 32, HID / 32);
    wh_prep<<<gridWh, 256>>>(Wh);

    // launches #4..: recurrence = per-step (k-split GEMM, activation)
    for (int t = 0; t < TT; t++) {
        gemm_step<<<dim3(HID / 128, KSPLIT), 256, DEC_SMEM>>>(t);
        act_step<<<(BB * HID) / 256, 256>>>(inputs, Wx, bias, hfin, t);
    }

    // decoder over all timesteps
    dim3 gridD(VOCAB / 128, TT);   // (16, 256)
    decoder_mma<<<gridD, 256, DEC_SMEM>>>(bd, out);
}

// round 15
// speedup vs baseline: 3.8047x; 1.1773x over previous
#include <cuda_runtime.h>
#include <cuda_bf16.h>
#include <cstdint>

#define VOCAB 2048
#define HID   1024
#define TT    256
#define BB    128
#define KSPLIT 8           // K-split factor for the per-step GEMM

// ---- persistent scratch (static device allocations are allowed) ----
__device__ __align__(128) __nv_bfloat16 g_Yhi[(size_t)TT * BB * HID];  // [t][m][k] hi plane, 64 MB
__device__ __align__(128) __nv_bfloat16 g_Ylo[(size_t)TT * BB * HID];  // lo plane, 64 MB
__device__ __align__(128) __nv_bfloat16 g_H0hi[BB * HID];              // h0 planes [m][k]
__device__ __align__(128) __nv_bfloat16 g_H0lo[BB * HID];
__device__ __align__(128) __nv_bfloat16 g_Whhi[(size_t)HID * HID];     // WhT hi [n][k], 2 MB
__device__ __align__(128) __nv_bfloat16 g_Whlo[(size_t)HID * HID];     // WhT lo [n][k], 2 MB
__device__ __align__(128) __nv_bfloat16 g_Bhi[(size_t)VOCAB * HID];    // WdT hi [n][k], 4 MB
__device__ __align__(128) __nv_bfloat16 g_Blo[(size_t)VOCAB * HID];    // WdT lo [n][k], 4 MB
__device__ __align__(128) float         g_PACC[KSPLIT * BB * HID];     // k-split partials, 4 MB

// ---------------- smem/async helpers ----------------
__device__ __forceinline__ uint32_t smem_u32(const void* p) {
    uint32_t a;
    asm("{ .reg .u64 t; cvta.to.shared.u64 t, %1; cvt.u32.u64 %0, t; }" : "=r"(a) : "l"(p));
    return a;
}
__device__ __forceinline__ void cp_async16(uint32_t sdst, const void* gsrc) {
    asm volatile("cp.async.cg.shared.global [%0], [%1], 16;" :: "r"(sdst), "l"(gsrc));
}
#define CP_COMMIT()  asm volatile("cp.async.commit_group;" ::: "memory")
#define CP_WAIT1()   asm volatile("cp.async.wait_group 1;" ::: "memory")

__device__ __forceinline__ void ldsm_x4(uint32_t r[4], uint32_t addr) {
    asm volatile("ldmatrix.sync.aligned.m8n8.x4.shared.b16 {%0,%1,%2,%3}, [%4];"
                 : "=r"(r[0]), "=r"(r[1]), "=r"(r[2]), "=r"(r[3]) : "r"(addr));
}
__device__ __forceinline__ void mma16816(float d[4], const uint32_t a[4], const uint32_t b0,
                                         const uint32_t b1) {
    asm volatile(
        "mma.sync.aligned.m16n8k16.row.col.f32.bf16.bf16.f32 "
        "{%0,%1,%2,%3}, {%4,%5,%6,%7}, {%8,%9}, {%0,%1,%2,%3};"
        : "+f"(d[0]), "+f"(d[1]), "+f"(d[2]), "+f"(d[3])
        : "r"(a[0]), "r"(a[1]), "r"(a[2]), "r"(a[3]), "r"(b0), "r"(b1));
}

// ---------------- init: split h0 (state, [m][k] row-major) into planes ----------------
__global__ void init_kernel(const float* __restrict__ state) {
    int idx = blockIdx.x * 256 + threadIdx.x;       // 131072 total
    float v = state[idx];
    __nv_bfloat16 h = __float2bfloat16_rn(v);
    __nv_bfloat16 l = __float2bfloat16_rn(v - __bfloat162float(h));
    g_H0hi[idx] = h;
    g_H0lo[idx] = l;
}

// ---------------- Wd prep (verified R4): transpose + bf16 hi/lo split ----------------
__global__ void __launch_bounds__(256)
wd_prep(const float* __restrict__ Wd) {
    __shared__ float ts[32][33];
    const int n0 = blockIdx.x * 32, k0 = blockIdx.y * 32;
    const int tx = threadIdx.x & 31, ty = threadIdx.x >> 5;
#pragma unroll
    for (int j = 0; j < 4; j++)
        ts[ty + 8 * j][tx] = Wd[(size_t)(k0 + ty + 8 * j) * VOCAB + n0 + tx];
    __syncthreads();
#pragma unroll
    for (int j = 0; j < 4; j++) {
        float v = ts[tx][ty + 8 * j];
        __nv_bfloat16 h = __float2bfloat16_rn(v);
        __nv_bfloat16 l = __float2bfloat16_rn(v - __bfloat162float(h));
        size_t o = (size_t)(n0 + ty + 8 * j) * HID + k0 + tx;
        g_Bhi[o] = h;
        g_Blo[o] = l;
    }
}

// ---------------- Wh prep: same pattern, square HID x HID (verified R13) ----------------
__global__ void __launch_bounds__(256)
wh_prep(const float* __restrict__ Wh) {
    __shared__ float ts[32][33];
    const int n0 = blockIdx.x * 32, k0 = blockIdx.y * 32;
    const int tx = threadIdx.x & 31, ty = threadIdx.x >> 5;
#pragma unroll
    for (int j = 0; j < 4; j++)
        ts[ty + 8 * j][tx] = Wh[(size_t)(k0 + ty + 8 * j) * HID + n0 + tx];
    __syncthreads();
#pragma unroll
    for (int j = 0; j < 4; j++) {
        float v = ts[tx][ty + 8 * j];
        __nv_bfloat16 h = __float2bfloat16_rn(v);
        __nv_bfloat16 l = __float2bfloat16_rn(v - __bfloat162float(h));
        size_t o = (size_t)(n0 + ty + 8 * j) * HID + k0 + tx;
        g_Whhi[o] = h;
        g_Whlo[o] = l;
    }
}

// =====================================================================
// Decoder GEMM geometry (verified): BM=128, BN=128, BK=64, 256 thr,
// stages Ah 16K | Al 16K | Bh 16K | Bl 16K = 64KB, double buffered.
// =====================================================================
#define DEC_STAGE 65536
#define DEC_SMEM  (2 * DEC_STAGE)

// =====================================================================
// gemm_step (R14-verified mainloop, BN=64): grid=(16, KSPLIT).
//   blockIdx.x = n-block (64 cols), blockIdx.y = ky (K range ky*128,+128)
//   Warp (wm 0..1, wn 0..3): m64 x n16 tile; per kk: 1 B ldsm per plane.
//   Stage: Ah 16K | Al 16K | Bh 8K | Bl 8K = 48KB, double buffered.
//   Partial (no bias) -> g_PACC[ky][m][n].
// =====================================================================
#define RN_STAGE 49152
#define RN_SMEM  (2 * RN_STAGE)

__global__ void __launch_bounds__(256, 1)
gemm_step(int t)
{
    extern __shared__ __align__(128) char dsm[];
    const uint32_t sbase = smem_u32(dsm);

    const int tid  = threadIdx.x;
    const int lane = tid & 31;
    const int wid  = tid >> 5;
    const int wm   = wid >> 2;          // 0..1
    const int wn   = wid & 3;           // 0..3
    const int n0g  = blockIdx.x * 64;   // hidden-col block (64 cols)
    const int ky   = blockIdx.y;        // k-split index
    const int kbase = ky * (HID / KSPLIT);   // 128 k per split

    const __nv_bfloat16* __restrict__ gAh =
        (t == 0) ? g_H0hi : (g_Yhi + (size_t)(t - 1) * BB * HID);
    const __nv_bfloat16* __restrict__ gAl =
        (t == 0) ? g_H0lo : (g_Ylo + (size_t)(t - 1) * BB * HID);
    const __nv_bfloat16* __restrict__ gBh = g_Whhi + (size_t)n0g * HID;
    const __nv_bfloat16* __restrict__ gBl = g_Whlo + (size_t)n0g * HID;

    auto issue_stage = [&](int stage, int k0) {
        const uint32_t sb = sbase + stage * RN_STAGE;
        // A planes: 2 x 128 rows x 8 chunks = 2048
#pragma unroll
        for (int j = 0; j < 8; j++) {
            int c   = tid + 256 * j;
            int pl  = c >> 10, cc = c & 1023;
            int row = cc >> 3, cx = cc & 7;
            uint32_t soff = (uint32_t)(row * 128 + ((cx * 16) ^ ((row & 7) << 4)));
            const __nv_bfloat16* src = pl ? gAl : gAh;
            cp_async16(sb + (pl ? 16384u : 0u) + soff,
                       src + (size_t)row * HID + k0 + cx * 8);
        }
        // B planes: 2 x 64 rows x 8 chunks = 1024
#pragma unroll
        for (int j = 0; j < 4; j++) {
            int c   = tid + 256 * j;
            int pl  = c >> 9, cc = c & 511;
            int row = cc >> 3, cx = cc & 7;
            uint32_t soff = (uint32_t)(row * 128 + ((cx * 16) ^ ((row & 7) << 4)));
            const __nv_bfloat16* src = pl ? gBl : gBh;
            cp_async16(sb + (pl ? 40960u : 32768u) + soff,
                       src + (size_t)row * HID + k0 + cx * 8);
        }
    };

    const int roffA = (lane & 7) + ((lane >> 3) & 1) * 8;
    const int kaddA = (lane >> 4) & 1;
    const int roffB = (lane & 7) + ((lane >> 4) & 1) * 8;
    const int kaddB = (lane >> 3) & 1;
    const int swx   = (lane & 7) << 4;
    const uint32_t rowA = (uint32_t)((wm * 64 + roffA) * 128);
    const uint32_t rowB = (uint32_t)((wn * 16 + roffB) * 128);

    float acc[4][2][4];
#pragma unroll
    for (int i = 0; i < 4; i++)
#pragma unroll
        for (int j = 0; j < 2; j++)
#pragma unroll
            for (int q = 0; q < 4; q++) acc[i][j][q] = 0.f;

    const int NIT = (HID / KSPLIT) / 64;    // 2 stages

    issue_stage(0, kbase);
    CP_COMMIT();

    for (int it = 0; it < NIT; it++) {
        if (it + 1 < NIT) issue_stage((it + 1) & 1, kbase + (it + 1) * 64);
        CP_COMMIT();
        CP_WAIT1();
        __syncthreads();

        const uint32_t sb = sbase + (it & 1) * RN_STAGE;
        const uint32_t pAh = sb,          pAl = sb + 16384;
        const uint32_t pBh = sb + 32768,  pBl = sb + 40960;

#pragma unroll
        for (int kk = 0; kk < 4; kk++) {
            const uint32_t kA = (uint32_t)((kk * 32 + kaddA * 16) ^ swx);
            const uint32_t kB = (uint32_t)((kk * 32 + kaddB * 16) ^ swx);

            uint32_t ah[4][4], al[4][4];
#pragma unroll
            for (int mt = 0; mt < 4; mt++) {
                ldsm_x4(ah[mt], pAh + rowA + mt * 2048 + kA);
                ldsm_x4(al[mt], pAl + rowA + mt * 2048 + kA);
            }
            uint32_t bh[4], bl[4];
            ldsm_x4(bh, pBh + rowB + kB);
            ldsm_x4(bl, pBl + rowB + kB);
#pragma unroll
            for (int mt = 0; mt < 4; mt++) {
#pragma unroll
                for (int nt = 0; nt < 2; nt++) {
                    mma16816(acc[mt][nt], ah[mt], bh[nt * 2], bh[nt * 2 + 1]);
                    mma16816(acc[mt][nt], ah[mt], bl[nt * 2], bl[nt * 2 + 1]);
                    mma16816(acc[mt][nt], al[mt], bh[nt * 2], bh[nt * 2 + 1]);
                }
            }
        }
        __syncthreads();
    }

    // ---- epilogue (decoder pattern): raw partials -> g_PACC[ky] ----
    float* __restrict__ pacc = g_PACC + (size_t)ky * BB * HID;
    const int rbase = wm * 64 + (lane >> 2);
    const int cbase = n0g + wn * 16 + (lane & 3) * 2;
#pragma unroll
    for (int mt = 0; mt < 4; mt++) {
#pragma unroll
        for (int nt = 0; nt < 2; nt++) {
            const int col = cbase + nt * 8;
            const int r0 = rbase + mt * 16;
            float2 v0 = make_float2(acc[mt][nt][0], acc[mt][nt][1]);
            float2 v1 = make_float2(acc[mt][nt][2], acc[mt][nt][3]);
            *(float2*)&pacc[(size_t)r0 * HID + col]       = v0;
            *(float2*)&pacc[(size_t)(r0 + 8) * HID + col] = v1;
        }
    }
}

// =====================================================================
// act_step: h = tanh(sum_ky PACC[ky] + bias + Wx[tok]) -> bf16 planes[t]
// grid = 512 x 256 thr; 1 elem/thread.
// =====================================================================
__global__ void __launch_bounds__(256)
act_step(const int* __restrict__ inputs, const float* __restrict__ Wx,
         const float* __restrict__ bias, float* __restrict__ hfin, int t)
{
    int idx = blockIdx.x * 256 + threadIdx.x;   // 0..131071
    int m = idx >> 10;
    int n = idx & 1023;
    int tok = inputs[m * TT + t];
    float s = bias[n] + Wx[(size_t)tok * HID + n];
#pragma unroll
    for (int ky = 0; ky < KSPLIT; ky++)
        s += g_PACC[(size_t)ky * BB * HID + idx];
    float h = tanhf(s);
    __nv_bfloat16 hh = __float2bfloat16_rn(h);
    __nv_bfloat16 hl = __float2bfloat16_rn(h - __bfloat162float(hh));
    size_t o = (size_t)t * BB * HID + idx;
    g_Yhi[o] = hh;
    g_Ylo[o] = hl;
    if (t == TT - 1) hfin[idx] = h;
}

// =====================================================================
// Decoder on mma.sync bf16 (2-term split) — unchanged (verified R4).
// =====================================================================
__global__ void __launch_bounds__(256, 1)
decoder_mma(const float* __restrict__ bd, float* __restrict__ out)
{
    extern __shared__ __align__(128) char dsm[];
    const uint32_t sbase = smem_u32(dsm);

    const int tid  = threadIdx.x;
    const int lane = tid & 31;
    const int wid  = tid >> 5;
    const int wm   = wid >> 2;          // 0..1
    const int wn   = wid & 3;           // 0..3
    const int mblk = blockIdx.y;        // 0..255 (= timestep)
    const int n0g  = blockIdx.x * 128;  // global n offset

    const __nv_bfloat16* __restrict__ gAh = g_Yhi + (size_t)mblk * 128 * HID;
    const __nv_bfloat16* __restrict__ gAl = g_Ylo + (size_t)mblk * 128 * HID;
    const __nv_bfloat16* __restrict__ gBh = g_Bhi + (size_t)n0g * HID;
    const __nv_bfloat16* __restrict__ gBl = g_Blo + (size_t)n0g * HID;

    auto issue_stage = [&](int stage, int k0) {
        const uint32_t sb = sbase + stage * DEC_STAGE;
#pragma unroll
        for (int j = 0; j < 4; j++) {
            int c   = tid + 256 * j;
            int row = c >> 3, cx = c & 7;
            uint32_t soff = (uint32_t)(row * 128 + ((cx * 16) ^ ((row & 7) << 4)));
            size_t goff = (size_t)row * HID + k0 + cx * 8;
            cp_async16(sb + soff,         gAh + goff);
            cp_async16(sb + 16384 + soff, gAl + goff);
            cp_async16(sb + 32768 + soff, gBh + goff);
            cp_async16(sb + 49152 + soff, gBl + goff);
        }
    };

    const int roffA = (lane & 7) + ((lane >> 3) & 1) * 8;
    const int kaddA = (lane >> 4) & 1;
    const int roffB = (lane & 7) + ((lane >> 4) & 1) * 8;
    const int kaddB = (lane >> 3) & 1;
    const int swx   = (lane & 7) << 4;
    const uint32_t rowA = (uint32_t)((wm * 64 + roffA) * 128);
    const uint32_t rowB = (uint32_t)((wn * 32 + roffB) * 128);

    float acc[4][4][4];
#pragma unroll
    for (int i = 0; i < 4; i++)
#pragma unroll
        for (int j = 0; j < 4; j++)
#pragma unroll
            for (int q = 0; q < 4; q++) acc[i][j][q] = 0.f;

    issue_stage(0, 0);
    CP_COMMIT();

    for (int it = 0; it < 16; it++) {
        if (it + 1 < 16) issue_stage((it + 1) & 1, (it + 1) * 64);
        CP_COMMIT();
        CP_WAIT1();
        __syncthreads();

        const uint32_t sb = sbase + (it & 1) * DEC_STAGE;
        const uint32_t pAh = sb,          pAl = sb + 16384;
        const uint32_t pBh = sb + 32768,  pBl = sb + 49152;

#pragma unroll
        for (int kk = 0; kk < 4; kk++) {
            const uint32_t kA = (uint32_t)((kk * 32 + kaddA * 16) ^ swx);
            const uint32_t kB = (uint32_t)((kk * 32 + kaddB * 16) ^ swx);

            uint32_t ah[4][4], al[4][4];
#pragma unroll
            for (int mt = 0; mt < 4; mt++) {
                ldsm_x4(ah[mt], pAh + rowA + mt * 2048 + kA);
                ldsm_x4(al[mt], pAl + rowA + mt * 2048 + kA);
            }
            uint32_t bh[2][4], bl[2][4];
#pragma unroll
            for (int np = 0; np < 2; np++) {
                ldsm_x4(bh[np], pBh + rowB + np * 2048 + kB);
                ldsm_x4(bl[np], pBl + rowB + np * 2048 + kB);
            }
#pragma unroll
            for (int mt = 0; mt < 4; mt++) {
#pragma unroll
                for (int nt = 0; nt < 4; nt++) {
                    const int np = nt >> 1, ni = (nt & 1) * 2;
                    mma16816(acc[mt][nt], ah[mt], bh[np][ni], bh[np][ni + 1]);
                    mma16816(acc[mt][nt], ah[mt], bl[np][ni], bl[np][ni + 1]);
                    mma16816(acc[mt][nt], al[mt], bh[np][ni], bh[np][ni + 1]);
                }
            }
        }
        __syncthreads();
    }

    const int rbase = mblk * 128 + wm * 64 + (lane >> 2);
    const int cbase = n0g + wn * 32 + (lane & 3) * 2;
#pragma unroll
    for (int mt = 0; mt < 4; mt++) {
#pragma unroll
        for (int nt = 0; nt < 4; nt++) {
            const int col = cbase + nt * 8;
            const float2 bv = *(const float2*)&bd[col];
            const int r0 = rbase + mt * 16;
            float2 v0 = make_float2(acc[mt][nt][0] + bv.x, acc[mt][nt][1] + bv.y);
            float2 v1 = make_float2(acc[mt][nt][2] + bv.x, acc[mt][nt][3] + bv.y);
            *(float2*)&out[(size_t)r0 * VOCAB + col]       = v0;
            *(float2*)&out[(size_t)(r0 + 8) * VOCAB + col] = v1;
        }
    }
}

extern "C" void kernel_launch(void* const* d_in, const int* in_sizes, int n_in,
                              void* d_out, int out_size)
{
    const int*   inputs = (const int*)  d_in[0];
    const float* state  = (const float*)d_in[1];
    const float* Wx     = (const float*)d_in[2];
    const float* Wh     = (const float*)d_in[3];
    const float* bias   = (const float*)d_in[4];
    const float* Wd     = (const float*)d_in[5];
    const float* bd     = (const float*)d_in[6];
    float* out = (float*)d_out;

    cudaFuncSetAttribute(gemm_step,   cudaFuncAttributeMaxDynamicSharedMemorySize, RN_SMEM);
    cudaFuncSetAttribute(decoder_mma, cudaFuncAttributeMaxDynamicSharedMemorySize, DEC_SMEM);

    size_t hf_off = (size_t)out_size - (size_t)BB * HID;
    float* hfin = out + hf_off;

    // launch #1: h0 planes
    init_kernel<<<(BB * HID) / 256, 256>>>(state);

    // launch #2: WdT planes
    dim3 gridWd(VOCAB / 32, HID / 32);
    wd_prep<<<gridWd, 256>>>(Wd);

    // launch #3: WhT planes
    dim3 gridWh(HID / 32, HID / 32);
    wh_prep<<<gridWh, 256>>>(Wh);

    // launches #4..: recurrence = per-step (k-split BN=64 GEMM, activation)
    for (int t = 0; t < TT; t++) {
        gemm_step<<<dim3(HID / 64, KSPLIT), 256, RN_SMEM>>>(t);
        act_step<<<(BB * HID) / 256, 256>>>(inputs, Wx, bias, hfin, t);
    }

    // decoder over all timesteps
    dim3 gridD(VOCAB / 128, TT);   // (16, 256)
    decoder_mma<<<gridD, 256, DEC_SMEM>>>(bd, out);
}